// round 16
// baseline (speedup 1.0000x reference)
#include <cuda_runtime.h>
#include <cuda_bf16.h>
#include <cuda_fp16.h>

#define HW     65536
#define BATCH  32
#define RANKN  4
#define CTXN   2048
#define NFEAT  106
#define SATT   53

// ---------------- scratch ----------------------------------------------------
__device__ float  g_raw[BATCH * NFEAT];        // GEMM output
__device__ float  g_coef[BATCH * RANKN * 12];  // affine coefficients (A,B,C complex x2)
__device__ float  g_wr[BATCH * RANKN];         // softmax rank weights (first 4 of 5)
__device__ float  g_gram[BATCH * 6];           // off-diag gram pairs 01,02,03,12,13,23
__device__ uint2  g_wsumh[BATCH * HW];         // 16 MB, [b][p] -> 4 halves (r0..r3)

__device__ __forceinline__ float siglog_dev(float x) {
    return copysignf(log1pf(fabsf(x)), x);
}

// ---------------- half2 <-> uint bit casts ------------------------------------
__device__ __forceinline__ unsigned h2_to_u(__half2 h) {
    return *reinterpret_cast<unsigned*>(&h);
}
__device__ __forceinline__ float2 u_to_f2(unsigned u) {
    __half2 h = *reinterpret_cast<__half2*>(&u);
    return __half22float2(h);
}

// ---------------- MUFU approx helpers ----------------------------------------
__device__ __forceinline__ float ex2_approx(float x) {
    float y; asm("ex2.approx.f32 %0, %1;" : "=f"(y) : "f"(x)); return y;
}
__device__ __forceinline__ float rcp_approx(float x) {
    float y; asm("rcp.approx.f32 %0, %1;" : "=f"(y) : "f"(x)); return y;
}
__device__ __forceinline__ float rsqrt_approx(float x) {
    float y; asm("rsqrt.approx.f32 %0, %1;" : "=f"(y) : "f"(x)); return y;
}

// ---------------- threefry2x32 with key (0, 42) -------------------------------
__device__ __forceinline__ unsigned rotl32(unsigned v, int d) {
    return (v << d) | (v >> (32 - d));
}
__device__ void threefry2x32_42(unsigned x0, unsigned x1, unsigned& o0, unsigned& o1) {
    const unsigned K0 = 0u, K1 = 42u;
    const unsigned K2 = K0 ^ K1 ^ 0x1BD11BDAu;
    const unsigned ks[3] = {K0, K1, K2};
    const int rotA[4] = {13, 15, 26, 6};
    const int rotB[4] = {17, 29, 16, 24};
    x0 += K0; x1 += K1;
    #pragma unroll
    for (int i = 0; i < 5; i++) {
        const int* rot = (i & 1) ? rotB : rotA;
        #pragma unroll
        for (int j = 0; j < 4; j++) {
            x0 += x1;
            x1 = rotl32(x1, rot[j]);
            x1 ^= x0;
        }
        x0 += ks[(i + 1) % 3];
        x1 += ks[(i + 2) % 3] + (unsigned)(i + 1);
    }
    o0 = x0; o1 = x1;
}

// ---------------- K1a: parallel GEMM, one block per (f, b) --------------------
__global__ void __launch_bounds__(128) k1a_kernel(const float* __restrict__ x,
                                                  const float* __restrict__ W,
                                                  const float* __restrict__ bias) {
    const int f = blockIdx.x, b = blockIdx.y;
    const int tid = threadIdx.x;
    const float* xr = x + (size_t)b * CTXN;
    const float* wr = W + (size_t)f * CTXN;
    float acc = 0.f;
    #pragma unroll
    for (int k = tid * 4; k < CTXN; k += 512) {   // 4 iters, 8 independent LDG.128
        const float4 xv = *reinterpret_cast<const float4*>(xr + k);
        const float4 wv = *reinterpret_cast<const float4*>(wr + k);
        acc = fmaf(xv.x, wv.x, acc);
        acc = fmaf(xv.y, wv.y, acc);
        acc = fmaf(xv.z, wv.z, acc);
        acc = fmaf(xv.w, wv.w, acc);
    }
    #pragma unroll
    for (int o = 16; o; o >>= 1) acc += __shfl_xor_sync(0xffffffffu, acc, o);
    __shared__ float sred[4];
    if ((tid & 31) == 0) sred[tid >> 5] = acc;
    __syncthreads();
    if (tid == 0)
        g_raw[b * NFEAT + f] = sred[0] + sred[1] + sred[2] + sred[3] + bias[f];
}

// ---------------- K1b: per-batch params (gating, coef, noise, softmax) --------
__global__ void __launch_bounds__(128) k1b_kernel(const float* __restrict__ extras) {
    const int b   = blockIdx.x;
    const int tid = threadIdx.x;
    __shared__ float sraw[112];
    __shared__ float sxt[56];
    __shared__ float swrank[5];
    __shared__ float sy[5];

    if (tid < NFEAT) sraw[tid] = g_raw[b * NFEAT + tid];
    if (tid < 6) g_gram[b * 6 + tid] = 0.f;    // zero gram for K3 atomics
    __syncthreads();

    if (tid < SATT) sxt[tid] = __fmul_rn(sraw[tid], siglog_dev(sraw[SATT + tid]));
    __syncthreads();

    // affine fold: w = A*z1 + B*z2 + C with A = s*(1-c), B = s*c, C = bias (complex)
    if (tid < 8) {
        const int r = tid >> 1, j = tid & 1;
        const float cre = __fadd_rn(sxt[r * 12 + 0 + j * 2 + 0], 0.5f);  // p_lerp + (0.5, 0)
        const float cim = sxt[r * 12 + 0 + j * 2 + 1];
        const float bre = sxt[r * 12 + 4 + j * 2 + 0];                   // p_bias
        const float bim = sxt[r * 12 + 4 + j * 2 + 1];
        const float sre = __fadd_rn(sxt[r * 12 + 8 + j * 2 + 0], 1.0f);  // p_scale + (1, 0)
        const float sim = sxt[r * 12 + 8 + j * 2 + 1];
        const float ocre = 1.0f - cre;
        const float Are = sre * ocre + sim * cim;
        const float Aim = sim * ocre - sre * cim;
        const float Bre = sre * cre - sim * cim;
        const float Bim = sre * cim + sim * cre;
        float* o = g_coef + (b * 4 + r) * 12 + j * 6;
        o[0] = Are; o[1] = Aim; o[2] = Bre; o[3] = Bim; o[4] = bre; o[5] = bim;
    }
    if (tid < 5) {
        float w = sxt[48 + tid];
        if (tid == 4) w = __fadd_rn(w, 0.5f);  // + 1/sqrt(RANK)
        swrank[tid] = w;
    }
    __syncthreads();

    if (tid < 5) {
        float m = 0.f;
        #pragma unroll
        for (int k = 0; k < 5; k++) m += swrank[k];
        m *= 0.2f;
        float v = 0.f;
        #pragma unroll
        for (int k = 0; k < 5; k++) { float d = swrank[k] - m; v += d * d; }
        const float stdv = sqrtf(v * 0.25f) + 1e-12f;   // ddof=1
        // jax.random.normal(key(42), (32,5)), jax_threefry_partitionable=True:
        // per element i: (o0,o1)=threefry2x32((0,42),(0,i)); bits = o0 ^ o1
        const int idx = b * 5 + tid;
        unsigned o0, o1;
        threefry2x32_42(0u, (unsigned)idx, o0, o1);
        unsigned bits = o0 ^ o1;
        float funi = __uint_as_float((bits >> 9) | 0x3f800000u) - 1.0f;  // [0,1)
        const float LOV = -0.99999994f;
        float u = fmaxf(LOV, __fadd_rn(__fmul_rn(funi, 2.0f), LOV));
        float nrm = 1.41421356237f * erfinvf(u);
        float logit = swrank[tid] + nrm * stdv * 0.01f;
        sy[tid] = siglog_dev(logit / extras[0]);
    }
    __syncthreads();

    if (tid == 0) {
        float mx = sy[0];
        #pragma unroll
        for (int k = 1; k < 5; k++) mx = fmaxf(mx, sy[k]);
        float s = 0.f, e[5];
        #pragma unroll
        for (int k = 0; k < 5; k++) { e[k] = expf(sy[k] - mx); s += e[k]; }
        float inv = 1.f / s;
        #pragma unroll
        for (int r = 0; r < 4; r++) g_wr[b * 4 + r] = e[r] * inv;
    }
}

// ---------------- K2: wsum planes (hot kernel, half output) -------------------
__device__ __forceinline__ float point_eval(float w0r, float w0i, float w1r, float w1i) {
    const float n2 = fmaf(w1i, w1i, fmaf(w1r, w1r, 1e-12f));
    const float ri = rsqrt_approx(n2);
    const float ws = fmaf(w0i, w1i, w0r * w1r) * ri;
    const float ex = ex2_approx(ws * -1.44269504088896f);  // e^{-ws}
    const float sig = rcp_approx(1.0f + ex);
    return ws * (sig + 0.001f);                            // stabilizer forward
}

__global__ void __launch_bounds__(128) k2_kernel(const float* __restrict__ wt) {
    __shared__ float sc[16 * 48];       // coefficients for this block's 16 batches
    const int tid = threadIdx.x;
    const int b0  = blockIdx.y * 16;
    for (int i = tid; i < 16 * 48; i += 128) sc[i] = g_coef[b0 * 48 + i];
    __syncthreads();

    const int p = blockIdx.x * 128 + tid;
    // z[i]: i = r*4 + e*2 + j  (e: z1/z2 endpoint, j: num/dir slot), (re, im)
    float2 z[16];
    #pragma unroll
    for (int i = 0; i < 16; i++)
        z[i] = *reinterpret_cast<const float2*>(wt + (size_t)i * (HW * 2) + (size_t)p * 2);

    #pragma unroll 1
    for (int bb = 0; bb < 16; bb++) {
        float vo[4];
        #pragma unroll
        for (int r = 0; r < 4; r++) {
            const float* cp = sc + (bb * 4 + r) * 12;
            const float4 c0 = *reinterpret_cast<const float4*>(cp + 0); // Are0 Aim0 Bre0 Bim0
            const float4 c1 = *reinterpret_cast<const float4*>(cp + 4); // Cre0 Cim0 Are1 Aim1
            const float4 c2 = *reinterpret_cast<const float4*>(cp + 8); // Bre1 Bim1 Cre1 Cim1
            const float2 z10 = z[r * 4 + 0], z11 = z[r * 4 + 1];
            const float2 z20 = z[r * 4 + 2], z21 = z[r * 4 + 3];
            float w0r = fmaf(c0.x, z10.x, c1.x);  w0r = fmaf(-c0.y, z10.y, w0r);
            w0r = fmaf(c0.z, z20.x, w0r);         w0r = fmaf(-c0.w, z20.y, w0r);
            float w0i = fmaf(c0.x, z10.y, c1.y);  w0i = fmaf(c0.y, z10.x, w0i);
            w0i = fmaf(c0.z, z20.y, w0i);         w0i = fmaf(c0.w, z20.x, w0i);
            float w1r = fmaf(c1.z, z11.x, c2.z);  w1r = fmaf(-c1.w, z11.y, w1r);
            w1r = fmaf(c2.x, z21.x, w1r);         w1r = fmaf(-c2.y, z21.y, w1r);
            float w1i = fmaf(c1.z, z11.y, c2.w);  w1i = fmaf(c1.w, z11.x, w1i);
            w1i = fmaf(c2.x, z21.y, w1i);         w1i = fmaf(c2.y, z21.x, w1i);
            vo[r] = point_eval(w0r, w0i, w1r, w1i);
        }
        uint2 pk;
        pk.x = h2_to_u(__floats2half2_rn(vo[0], vo[1]));
        pk.y = h2_to_u(__floats2half2_rn(vo[2], vo[3]));
        g_wsumh[(size_t)(b0 + bb) * HW + p] = pk;
    }
}

// ---------------- K3: gram, loads hoisted (4 indep LDG.128 per thread) --------
__global__ void __launch_bounds__(256) k3_kernel() {
    const int b   = blockIdx.y;
    const int tid = threadIdx.x;
    const uint4* wp = reinterpret_cast<const uint4*>(g_wsumh + (size_t)b * HW) +
                      blockIdx.x * 1024 + tid;
    uint4 q[4];
    #pragma unroll
    for (int it = 0; it < 4; it++) q[it] = wp[it * 256];   // front-batched, MLP=4
    float a[6] = {0.f, 0.f, 0.f, 0.f, 0.f, 0.f};
    #pragma unroll
    for (int it = 0; it < 4; it++) {
        {
            const float2 v01 = u_to_f2(q[it].x);
            const float2 v23 = u_to_f2(q[it].y);
            a[0] = fmaf(v01.x, v01.y, a[0]);
            a[1] = fmaf(v01.x, v23.x, a[1]);
            a[2] = fmaf(v01.x, v23.y, a[2]);
            a[3] = fmaf(v01.y, v23.x, a[3]);
            a[4] = fmaf(v01.y, v23.y, a[4]);
            a[5] = fmaf(v23.x, v23.y, a[5]);
        }
        {
            const float2 v01 = u_to_f2(q[it].z);
            const float2 v23 = u_to_f2(q[it].w);
            a[0] = fmaf(v01.x, v01.y, a[0]);
            a[1] = fmaf(v01.x, v23.x, a[1]);
            a[2] = fmaf(v01.x, v23.y, a[2]);
            a[3] = fmaf(v01.y, v23.x, a[3]);
            a[4] = fmaf(v01.y, v23.y, a[4]);
            a[5] = fmaf(v23.x, v23.y, a[5]);
        }
    }
    __shared__ float sred[8][6];
    const int warp = tid >> 5, lane = tid & 31;
    #pragma unroll
    for (int k = 0; k < 6; k++) {
        float v = a[k];
        #pragma unroll
        for (int o = 16; o; o >>= 1) v += __shfl_xor_sync(0xffffffffu, v, o);
        if (lane == 0) sred[warp][k] = v;
    }
    __syncthreads();
    if (tid < 6) {
        float s = 0.f;
        #pragma unroll
        for (int w = 0; w < 8; w++) s += sred[w][tid];
        atomicAdd(&g_gram[b * 6 + tid], s);
    }
}

// ---------------- K5: inline evec fold + out = dot(evec, wsumh), 8 px/thread --
__global__ void __launch_bounds__(256) k5_kernel(float* __restrict__ out) {
    const int b = blockIdx.y;
    const float g01 = g_gram[b * 6 + 0], g02 = g_gram[b * 6 + 1], g03 = g_gram[b * 6 + 2];
    const float g12 = g_gram[b * 6 + 3], g13 = g_gram[b * 6 + 4], g23 = g_gram[b * 6 + 5];
    const float4 w = *reinterpret_cast<const float4*>(g_wr + b * 4);
    const float cf = 0.05f;  // (REPULSION / sqrt(RANK)) / (RANK - 1)
    float4 e;
    e.x = w.x - cf * (w.y * g01 + w.z * g02 + w.w * g03);
    e.y = w.y - cf * (w.x * g01 + w.z * g12 + w.w * g13);
    e.z = w.z - cf * (w.x * g02 + w.y * g12 + w.w * g23);
    e.w = w.w - cf * (w.x * g03 + w.y * g13 + w.z * g23);

    const int p0 = (blockIdx.x * 256 + threadIdx.x) * 8;
    const uint4* wp = reinterpret_cast<const uint4*>(g_wsumh + (size_t)b * HW + p0);
    uint4 q[4];
    #pragma unroll
    for (int i = 0; i < 4; i++) q[i] = wp[i];   // 4 independent LDG.128 (8 pixels)
    float o[8];
    #pragma unroll
    for (int i = 0; i < 4; i++) {
        {
            const float2 v01 = u_to_f2(q[i].x);
            const float2 v23 = u_to_f2(q[i].y);
            o[i * 2 + 0] = fmaf(e.w, v23.y, fmaf(e.z, v23.x, fmaf(e.y, v01.y, e.x * v01.x)));
        }
        {
            const float2 v01 = u_to_f2(q[i].z);
            const float2 v23 = u_to_f2(q[i].w);
            o[i * 2 + 1] = fmaf(e.w, v23.y, fmaf(e.z, v23.x, fmaf(e.y, v01.y, e.x * v01.x)));
        }
    }
    float4* op = reinterpret_cast<float4*>(out + (size_t)b * HW + p0);
    op[0] = make_float4(o[0], o[1], o[2], o[3]);
    op[1] = make_float4(o[4], o[5], o[6], o[7]);
}

// ---------------- launch ------------------------------------------------------
extern "C" void kernel_launch(void* const* d_in, const int* in_sizes, int n_in,
                              void* d_out, int out_size) {
    const float* x      = (const float*)d_in[0];
    const float* ctx_w  = (const float*)d_in[1];
    const float* ctx_b  = (const float*)d_in[2];
    const float* wts    = (const float*)d_in[3];
    const float* extras = (const float*)d_in[4];
    float* out = (float*)d_out;

    k1a_kernel<<<dim3(NFEAT, BATCH), 128>>>(x, ctx_w, ctx_b);
    k1b_kernel<<<BATCH, 128>>>(extras);
    k2_kernel<<<dim3(HW / 128, 2), 128>>>(wts);
    k3_kernel<<<dim3(32, BATCH), 256>>>();
    k5_kernel<<<dim3(HW / 2048, BATCH), 256>>>(out);
}

// round 17
// speedup vs baseline: 1.1316x; 1.1316x over previous
#include <cuda_runtime.h>
#include <cuda_bf16.h>
#include <cuda_fp16.h>

#define HW     65536
#define BATCH  32
#define RANKN  4
#define CTXN   2048
#define NFEAT  106
#define SATT   53

// ---------------- scratch ----------------------------------------------------
__device__ float  g_raw[BATCH * NFEAT];        // GEMM output
__device__ float  g_gram[BATCH * 6];           // off-diag gram pairs 01,02,03,12,13,23
__device__ uint2  g_wsumh[BATCH * HW];         // 16 MB, [b][p] -> 4 halves (r0..r3)

__device__ __forceinline__ float siglog_dev(float x) {
    return copysignf(log1pf(fabsf(x)), x);
}

// ---------------- half2 <-> uint bit casts ------------------------------------
__device__ __forceinline__ unsigned h2_to_u(__half2 h) {
    return *reinterpret_cast<unsigned*>(&h);
}
__device__ __forceinline__ float2 u_to_f2(unsigned u) {
    __half2 h = *reinterpret_cast<__half2*>(&u);
    return __half22float2(h);
}

// ---------------- MUFU approx helpers ----------------------------------------
__device__ __forceinline__ float rsqrt_approx(float x) {
    float y; asm("rsqrt.approx.f32 %0, %1;" : "=f"(y) : "f"(x)); return y;
}
__device__ __forceinline__ float tanh_approx(float x) {
    float y; asm("tanh.approx.f32 %0, %1;" : "=f"(y) : "f"(x)); return y;
}

// ---------------- threefry2x32 with key (0, 42) -------------------------------
__device__ __forceinline__ unsigned rotl32(unsigned v, int d) {
    return (v << d) | (v >> (32 - d));
}
__device__ void threefry2x32_42(unsigned x0, unsigned x1, unsigned& o0, unsigned& o1) {
    const unsigned K0 = 0u, K1 = 42u;
    const unsigned K2 = K0 ^ K1 ^ 0x1BD11BDAu;
    const unsigned ks[3] = {K0, K1, K2};
    const int rotA[4] = {13, 15, 26, 6};
    const int rotB[4] = {17, 29, 16, 24};
    x0 += K0; x1 += K1;
    #pragma unroll
    for (int i = 0; i < 5; i++) {
        const int* rot = (i & 1) ? rotB : rotA;
        #pragma unroll
        for (int j = 0; j < 4; j++) {
            x0 += x1;
            x1 = rotl32(x1, rot[j]);
            x1 ^= x0;
        }
        x0 += ks[(i + 1) % 3];
        x1 += ks[(i + 2) % 3] + (unsigned)(i + 1);
    }
    o0 = x0; o1 = x1;
}

// ---------------- K1a: parallel GEMM, one block per (f, b); zeroes gram -------
__global__ void __launch_bounds__(128) k1a_kernel(const float* __restrict__ x,
                                                  const float* __restrict__ W,
                                                  const float* __restrict__ bias) {
    const int f = blockIdx.x, b = blockIdx.y;
    const int tid = threadIdx.x;
    if (f == 0 && tid < 6) g_gram[b * 6 + tid] = 0.f;   // re-zero every call
    const float* xr = x + (size_t)b * CTXN;
    const float* wr = W + (size_t)f * CTXN;
    float acc = 0.f;
    #pragma unroll
    for (int k = tid * 4; k < CTXN; k += 512) {   // 4 iters, 8 independent LDG.128
        const float4 xv = *reinterpret_cast<const float4*>(xr + k);
        const float4 wv = *reinterpret_cast<const float4*>(wr + k);
        acc = fmaf(xv.x, wv.x, acc);
        acc = fmaf(xv.y, wv.y, acc);
        acc = fmaf(xv.z, wv.z, acc);
        acc = fmaf(xv.w, wv.w, acc);
    }
    #pragma unroll
    for (int o = 16; o; o >>= 1) acc += __shfl_xor_sync(0xffffffffu, acc, o);
    __shared__ float sred[4];
    if ((tid & 31) == 0) sred[tid >> 5] = acc;
    __syncthreads();
    if (tid == 0)
        g_raw[b * NFEAT + f] = sred[0] + sred[1] + sred[2] + sred[3] + bias[f];
}

// ---------------- K2: coef prologue + wsum planes (half output) ---------------
__device__ __forceinline__ float point_eval(float w0r, float w0i, float w1r, float w1i) {
    const float n2 = fmaf(w1i, w1i, fmaf(w1r, w1r, 1e-12f));
    const float ri = rsqrt_approx(n2);
    const float ws = fmaf(w0i, w1i, w0r * w1r) * ri;
    const float th = tanh_approx(ws * 0.5f);
    return ws * fmaf(0.5f, th, 0.501f);   // ws*(sigmoid(ws) + 0.001)
}

__global__ void __launch_bounds__(128) k2_kernel(const float* __restrict__ wt) {
    __shared__ float sc[16 * 48];       // coefficients for this block's 16 batches
    const int tid = threadIdx.x;
    const int b0  = blockIdx.y * 16;

    // prologue: thread t computes (bb = t>>3, r = (t>>1)&3, j = t&1) coefficients
    {
        const int bb = tid >> 3, r = (tid >> 2) & 1 ? 0 : 0;  // placeholder (see below)
        const int pair = tid & 7;
        const int rr = pair >> 1, j = pair & 1;
        const float* raw = g_raw + (b0 + bb) * NFEAT;
        const int i0 = rr * 12 + 0 + j * 2;   // p_lerp
        const int i1 = rr * 12 + 4 + j * 2;   // p_bias
        const int i2 = rr * 12 + 8 + j * 2;   // p_scale
        const float cre = __fadd_rn(__fmul_rn(raw[i0 + 0], siglog_dev(raw[SATT + i0 + 0])), 0.5f);
        const float cim = __fmul_rn(raw[i0 + 1], siglog_dev(raw[SATT + i0 + 1]));
        const float bre = __fmul_rn(raw[i1 + 0], siglog_dev(raw[SATT + i1 + 0]));
        const float bim = __fmul_rn(raw[i1 + 1], siglog_dev(raw[SATT + i1 + 1]));
        const float sre = __fadd_rn(__fmul_rn(raw[i2 + 0], siglog_dev(raw[SATT + i2 + 0])), 1.0f);
        const float sim = __fmul_rn(raw[i2 + 1], siglog_dev(raw[SATT + i2 + 1]));
        const float ocre = 1.0f - cre;
        float* o = sc + (bb * 4 + rr) * 12 + j * 6;
        o[0] = sre * ocre + sim * cim;   // Are
        o[1] = sim * ocre - sre * cim;   // Aim
        o[2] = sre * cre - sim * cim;    // Bre
        o[3] = sre * cim + sim * cre;    // Bim
        o[4] = bre;                      // Cre
        o[5] = bim;                      // Cim
    }
    __syncthreads();

    const int p = blockIdx.x * 128 + tid;
    // z[i]: i = r*4 + e*2 + j  (e: z1/z2 endpoint, j: num/dir slot), (re, im)
    float2 z[16];
    #pragma unroll
    for (int i = 0; i < 16; i++)
        z[i] = *reinterpret_cast<const float2*>(wt + (size_t)i * (HW * 2) + (size_t)p * 2);

    #pragma unroll 1
    for (int bb = 0; bb < 16; bb++) {
        float vo[4];
        #pragma unroll
        for (int r = 0; r < 4; r++) {
            const float* cp = sc + (bb * 4 + r) * 12;
            const float4 c0 = *reinterpret_cast<const float4*>(cp + 0); // Are0 Aim0 Bre0 Bim0
            const float4 c1 = *reinterpret_cast<const float4*>(cp + 4); // Cre0 Cim0 Are1 Aim1
            const float4 c2 = *reinterpret_cast<const float4*>(cp + 8); // Bre1 Bim1 Cre1 Cim1
            const float2 z10 = z[r * 4 + 0], z11 = z[r * 4 + 1];
            const float2 z20 = z[r * 4 + 2], z21 = z[r * 4 + 3];
            float w0r = fmaf(c0.x, z10.x, c1.x);  w0r = fmaf(-c0.y, z10.y, w0r);
            w0r = fmaf(c0.z, z20.x, w0r);         w0r = fmaf(-c0.w, z20.y, w0r);
            float w0i = fmaf(c0.x, z10.y, c1.y);  w0i = fmaf(c0.y, z10.x, w0i);
            w0i = fmaf(c0.z, z20.y, w0i);         w0i = fmaf(c0.w, z20.x, w0i);
            float w1r = fmaf(c1.z, z11.x, c2.z);  w1r = fmaf(-c1.w, z11.y, w1r);
            w1r = fmaf(c2.x, z21.x, w1r);         w1r = fmaf(-c2.y, z21.y, w1r);
            float w1i = fmaf(c1.z, z11.y, c2.w);  w1i = fmaf(c1.w, z11.x, w1i);
            w1i = fmaf(c2.x, z21.y, w1i);         w1i = fmaf(c2.y, z21.x, w1i);
            vo[r] = point_eval(w0r, w0i, w1r, w1i);
        }
        uint2 pk;
        pk.x = h2_to_u(__floats2half2_rn(vo[0], vo[1]));
        pk.y = h2_to_u(__floats2half2_rn(vo[2], vo[3]));
        g_wsumh[(size_t)(b0 + bb) * HW + p] = pk;
    }
}

// ---------------- K3: per-batch off-diagonal gram -----------------------------
__global__ void __launch_bounds__(256) k3_kernel() {
    const int b   = blockIdx.y;
    const int tid = threadIdx.x;
    const uint4* wp = reinterpret_cast<const uint4*>(g_wsumh + (size_t)b * HW) +
                      blockIdx.x * 1024 + tid;
    uint4 q[4];
    #pragma unroll
    for (int it = 0; it < 4; it++) q[it] = wp[it * 256];
    float a[6] = {0.f, 0.f, 0.f, 0.f, 0.f, 0.f};
    #pragma unroll
    for (int it = 0; it < 4; it++) {
        {
            const float2 v01 = u_to_f2(q[it].x);
            const float2 v23 = u_to_f2(q[it].y);
            a[0] = fmaf(v01.x, v01.y, a[0]);
            a[1] = fmaf(v01.x, v23.x, a[1]);
            a[2] = fmaf(v01.x, v23.y, a[2]);
            a[3] = fmaf(v01.y, v23.x, a[3]);
            a[4] = fmaf(v01.y, v23.y, a[4]);
            a[5] = fmaf(v23.x, v23.y, a[5]);
        }
        {
            const float2 v01 = u_to_f2(q[it].z);
            const float2 v23 = u_to_f2(q[it].w);
            a[0] = fmaf(v01.x, v01.y, a[0]);
            a[1] = fmaf(v01.x, v23.x, a[1]);
            a[2] = fmaf(v01.x, v23.y, a[2]);
            a[3] = fmaf(v01.y, v23.x, a[3]);
            a[4] = fmaf(v01.y, v23.y, a[4]);
            a[5] = fmaf(v23.x, v23.y, a[5]);
        }
    }
    __shared__ float sred[8][6];
    const int warp = tid >> 5, lane = tid & 31;
    #pragma unroll
    for (int k = 0; k < 6; k++) {
        float v = a[k];
        #pragma unroll
        for (int o = 16; o; o >>= 1) v += __shfl_xor_sync(0xffffffffu, v, o);
        if (lane == 0) sred[warp][k] = v;
    }
    __syncthreads();
    if (tid < 6) {
        float s = 0.f;
        #pragma unroll
        for (int w = 0; w < 8; w++) s += sred[w][tid];
        atomicAdd(&g_gram[b * 6 + tid], s);
    }
}

// ---------------- K5: inline wr+evec + out = dot(evec, wsumh), 8 px/thread ----
__global__ void __launch_bounds__(256) k5_kernel(float* __restrict__ out,
                                                 const float* __restrict__ extras) {
    const int b = blockIdx.y;
    const int tid = threadIdx.x;
    __shared__ float sy[5];
    __shared__ float se[4];
    if (tid < 5) {
        const float* raw = g_raw + b * NFEAT;
        float wrk[5];
        #pragma unroll
        for (int k = 0; k < 5; k++) {
            float w = __fmul_rn(raw[48 + k], siglog_dev(raw[SATT + 48 + k]));
            if (k == 4) w = __fadd_rn(w, 0.5f);
            wrk[k] = w;
        }
        float m = 0.f;
        #pragma unroll
        for (int k = 0; k < 5; k++) m += wrk[k];
        m *= 0.2f;
        float v = 0.f;
        #pragma unroll
        for (int k = 0; k < 5; k++) { float d = wrk[k] - m; v += d * d; }
        const float stdv = sqrtf(v * 0.25f) + 1e-12f;
        const int idx = b * 5 + tid;
        unsigned o0, o1;
        threefry2x32_42(0u, (unsigned)idx, o0, o1);
        unsigned bits = o0 ^ o1;
        float funi = __uint_as_float((bits >> 9) | 0x3f800000u) - 1.0f;
        const float LOV = -0.99999994f;
        float u = fmaxf(LOV, __fadd_rn(__fmul_rn(funi, 2.0f), LOV));
        float nrm = 1.41421356237f * erfinvf(u);
        float logit = wrk[tid] + nrm * stdv * 0.01f;
        sy[tid] = siglog_dev(logit / extras[0]);
    }
    __syncthreads();
    if (tid == 0) {
        float mx = sy[0];
        #pragma unroll
        for (int k = 1; k < 5; k++) mx = fmaxf(mx, sy[k]);
        float s = 0.f, e5[5];
        #pragma unroll
        for (int k = 0; k < 5; k++) { e5[k] = expf(sy[k] - mx); s += e5[k]; }
        float inv = 1.f / s;
        const float w0 = e5[0] * inv, w1 = e5[1] * inv, w2 = e5[2] * inv, w3 = e5[3] * inv;
        const float g01 = g_gram[b * 6 + 0], g02 = g_gram[b * 6 + 1], g03 = g_gram[b * 6 + 2];
        const float g12 = g_gram[b * 6 + 3], g13 = g_gram[b * 6 + 4], g23 = g_gram[b * 6 + 5];
        const float cf = 0.05f;  // (REPULSION / sqrt(RANK)) / (RANK - 1)
        se[0] = w0 - cf * (w1 * g01 + w2 * g02 + w3 * g03);
        se[1] = w1 - cf * (w0 * g01 + w2 * g12 + w3 * g13);
        se[2] = w2 - cf * (w0 * g02 + w1 * g12 + w3 * g23);
        se[3] = w3 - cf * (w0 * g03 + w1 * g13 + w2 * g23);
    }
    __syncthreads();
    const float4 e = *reinterpret_cast<const float4*>(se);

    const int p0 = (blockIdx.x * 256 + tid) * 8;
    const uint4* wp = reinterpret_cast<const uint4*>(g_wsumh + (size_t)b * HW + p0);
    uint4 q[4];
    #pragma unroll
    for (int i = 0; i < 4; i++) q[i] = wp[i];
    float o[8];
    #pragma unroll
    for (int i = 0; i < 4; i++) {
        {
            const float2 v01 = u_to_f2(q[i].x);
            const float2 v23 = u_to_f2(q[i].y);
            o[i * 2 + 0] = fmaf(e.w, v23.y, fmaf(e.z, v23.x, fmaf(e.y, v01.y, e.x * v01.x)));
        }
        {
            const float2 v01 = u_to_f2(q[i].z);
            const float2 v23 = u_to_f2(q[i].w);
            o[i * 2 + 1] = fmaf(e.w, v23.y, fmaf(e.z, v23.x, fmaf(e.y, v01.y, e.x * v01.x)));
        }
    }
    float4* op = reinterpret_cast<float4*>(out + (size_t)b * HW + p0);
    op[0] = make_float4(o[0], o[1], o[2], o[3]);
    op[1] = make_float4(o[4], o[5], o[6], o[7]);
}

// ---------------- launch ------------------------------------------------------
extern "C" void kernel_launch(void* const* d_in, const int* in_sizes, int n_in,
                              void* d_out, int out_size) {
    const float* x      = (const float*)d_in[0];
    const float* ctx_w  = (const float*)d_in[1];
    const float* ctx_b  = (const float*)d_in[2];
    const float* wts    = (const float*)d_in[3];
    const float* extras = (const float*)d_in[4];
    float* out = (float*)d_out;

    k1a_kernel<<<dim3(NFEAT, BATCH), 128>>>(x, ctx_w, ctx_b);
    k2_kernel<<<dim3(HW / 128, 2), 128>>>(wts);
    k3_kernel<<<dim3(32, BATCH), 256>>>();
    k5_kernel<<<dim3(HW / 2048, BATCH), 256>>>(out, extras);
}